// round 2
// baseline (speedup 1.0000x reference)
#include <cuda_runtime.h>

// ---------------------------------------------------------------------------
// MixtureDecoder: soft-tree gating -> leaf mixture -> 3x ConvTranspose2d(4,2,1)
// Shapes: x[512,128], gw[128,31], gb[31], z[8192,32],
//         w1[128,128,4,4], b1[128], w2[128,64,4,4], b2[64], w3[64,3,4,4], b3[3]
// out: [512,3,64,64] fp32
// ---------------------------------------------------------------------------

#define B_ 512

__device__ float g_lp[B_ * 32];                   // leaf probs
__device__ float g_x0[B_ * 128 * 8 * 8];          // mixture output (conv1 in)
__device__ float g_a1[(size_t)B_ * 128 * 16 * 16];// conv1 out (relu)
__device__ float g_a2[(size_t)B_ * 64 * 32 * 32]; // conv2 out (relu)

// ---------------- gating + tree leaf probabilities -------------------------
__global__ void lp_kernel(const float* __restrict__ x,
                          const float* __restrict__ gw,
                          const float* __restrict__ gb) {
    int b = blockIdx.x;
    int lane = threadIdx.x;               // 32 threads
    __shared__ float g_sh[31];

    if (lane < 31) {
        float p = gb[lane];
        const float* xb = x + b * 128;
        #pragma unroll 8
        for (int i = 0; i < 128; ++i)
            p += xb[i] * gw[i * 31 + lane];   // xb[i] broadcast, gw coalesced
        g_sh[lane] = 1.0f / (1.0f + expf(-p));
    }
    __syncwarp();

    // leaf 'lane' : bits msb->lsb choose gate (0) or 1-gate (1)
    float lp = 1.0f;
    int prefix = 0;
    #pragma unroll
    for (int d = 1; d <= 5; ++d) {
        float gate = g_sh[(1 << (d - 1)) - 1 + prefix];
        int bit = (lane >> (5 - d)) & 1;
        lp *= bit ? (1.0f - gate) : gate;
        prefix = (prefix << 1) | bit;
    }
    g_lp[b * 32 + lane] = lp;
}

// ---------------- mixture: out0[b,f] = sum_l lp[b,l] * z[f,l] --------------
__global__ __launch_bounds__(256) void mix_kernel(const float* __restrict__ z) {
    int f = blockIdx.x * 256 + threadIdx.x;   // feature
    int b0 = blockIdx.y * 32;                 // batch tile
    __shared__ float s_lp[32][32];
    for (int i = threadIdx.x; i < 1024; i += 256)
        s_lp[i >> 5][i & 31] = g_lp[b0 * 32 + i];
    __syncthreads();

    float zr[32];
    #pragma unroll
    for (int l4 = 0; l4 < 8; ++l4) {
        float4 v = *reinterpret_cast<const float4*>(z + (size_t)f * 32 + l4 * 4);
        zr[l4 * 4 + 0] = v.x; zr[l4 * 4 + 1] = v.y;
        zr[l4 * 4 + 2] = v.z; zr[l4 * 4 + 3] = v.w;
    }
    #pragma unroll 4
    for (int bi = 0; bi < 32; ++bi) {
        float acc = 0.0f;
        #pragma unroll
        for (int l = 0; l < 32; ++l) acc += zr[l] * s_lp[bi][l];
        g_x0[(size_t)(b0 + bi) * 8192 + f] = acc;
    }
}

// ---------------- ConvTranspose2d(k=4, s=2, p=1) direct kernel -------------
// out[oy,ox] = sum_{iy,ix} in[iy,ix] * w[ic,oc,ky,kx], ky = oy+1-2*iy (0..3)
// Each 2x2 output quad (jy,jx) reads the 3x3 input window centered at (jy,jx).
// Thread tile: TOC out-channels x Q x-adjacent quads (intensity ~3.1 FMA/LDS-f).
template <int IC, int OC, int IH, int IW, int OHT, int OCT, int TOC, int Q,
          int ICC, bool RELU, int NT>
__global__ __launch_bounds__(NT) void convt_kernel(
    const float* __restrict__ in, const float* __restrict__ W,
    const float* __restrict__ bias, float* __restrict__ out) {
    constexpr int OH = 2 * IH, OW = 2 * IW;
    constexpr int NQY = OHT / 2, NQX = OW / 2, XG = NQX / Q;
    constexpr int SROWS = NQY + 2, SCOLS = IW + 2;
    constexpr int IN_ELE = IC * SROWS * SCOLS;
    constexpr int WSTR = 17;                       // pad: conflict-free

    extern __shared__ float smem[];
    float* s_in = smem;                 // [IC][SROWS][SCOLS], zero halo
    float* s_w = smem + IN_ELE;         // [ICC][OCT][WSTR]

    const int b = blockIdx.x;
    const int jy0 = blockIdx.y * NQY;   // quad-row base (input row units)
    const int oc0 = blockIdx.z * OCT;

    const int tid = threadIdx.x;
    const int sp = tid % (NQY * XG);
    const int ocg = tid / (NQY * XG);
    const int qxg = sp % XG;
    const int qy = sp / XG;
    const int qx0 = qxg * Q;

    // stage input tile with zero halo
    const float* inb = in + (size_t)b * IC * IH * IW;
    for (int idx = tid; idx < IN_ELE; idx += NT) {
        int ic = idx / (SROWS * SCOLS);
        int r = idx % (SROWS * SCOLS);
        int ry = r / SCOLS, cx = r % SCOLS;
        int iy = jy0 - 1 + ry, ix = cx - 1;
        float v = 0.0f;
        if (iy >= 0 && iy < IH && ix >= 0 && ix < IW)
            v = inb[(ic * IH + iy) * IW + ix];
        s_in[idx] = v;
    }

    float acc[TOC][Q][4];
    #pragma unroll
    for (int t = 0; t < TOC; ++t)
        #pragma unroll
        for (int q = 0; q < Q; ++q)
            #pragma unroll
            for (int k = 0; k < 4; ++k) acc[t][q][k] = 0.0f;

    for (int ic0 = 0; ic0 < IC; ic0 += ICC) {
        __syncthreads();   // also covers initial s_in staging
        // stage weight chunk: s_w[(icl*OCT+ol)*WSTR + k] = W[(ic0+icl, oc0+ol, k)]
        for (int idx = tid; idx < ICC * OCT * 16; idx += NT) {
            int k = idx & 15;
            int ol = (idx >> 4) % OCT;
            int icl = idx / (16 * OCT);
            s_w[(icl * OCT + ol) * WSTR + k] =
                W[((size_t)(ic0 + icl) * OC + oc0 + ol) * 16 + k];
        }
        __syncthreads();

        for (int icl = 0; icl < ICC; ++icl) {
            const float* si =
                s_in + (ic0 + icl) * (SROWS * SCOLS) + qy * SCOLS + qx0;
            float iv[3][Q + 2];
            #pragma unroll
            for (int r = 0; r < 3; ++r)
                #pragma unroll
                for (int c = 0; c < Q + 2; ++c) iv[r][c] = si[r * SCOLS + c];

            #pragma unroll
            for (int t = 0; t < TOC; ++t) {
                const float* wp = s_w + (icl * OCT + ocg * TOC + t) * WSTR;
                float w[16];
                #pragma unroll
                for (int k = 0; k < 16; ++k) w[k] = wp[k];
                #pragma unroll
                for (int q = 0; q < Q; ++q) {
                    float* a = acc[t][q];
                    // (py=0,px=0): taps (iy=jy-1,ky=3),(jy,1) x (ix=jx-1,kx=3),(jx,1)
                    a[0] += iv[0][q] * w[15];     a[0] += iv[0][q + 1] * w[13];
                    a[0] += iv[1][q] * w[7];      a[0] += iv[1][q + 1] * w[5];
                    // (0,1)
                    a[1] += iv[0][q + 1] * w[14]; a[1] += iv[0][q + 2] * w[12];
                    a[1] += iv[1][q + 1] * w[6];  a[1] += iv[1][q + 2] * w[4];
                    // (1,0)
                    a[2] += iv[1][q] * w[11];     a[2] += iv[1][q + 1] * w[9];
                    a[2] += iv[2][q] * w[3];      a[2] += iv[2][q + 1] * w[1];
                    // (1,1)
                    a[3] += iv[1][q + 1] * w[10]; a[3] += iv[1][q + 2] * w[8];
                    a[3] += iv[2][q + 1] * w[2];  a[3] += iv[2][q + 2] * w[0];
                }
            }
        }
    }

    float* outb = out + (size_t)b * OC * OH * OW;
    #pragma unroll
    for (int t = 0; t < TOC; ++t) {
        int oc = oc0 + ocg * TOC + t;
        float bv = bias[oc];
        #pragma unroll
        for (int q = 0; q < Q; ++q) {
            int ox = 2 * (qx0 + q);
            #pragma unroll
            for (int py = 0; py < 2; ++py) {
                int oy = 2 * (jy0 + qy) + py;
                float v0 = acc[t][q][py * 2 + 0] + bv;
                float v1 = acc[t][q][py * 2 + 1] + bv;
                if (RELU) { v0 = fmaxf(v0, 0.0f); v1 = fmaxf(v1, 0.0f); }
                *reinterpret_cast<float2*>(outb + ((size_t)oc * OH + oy) * OW + ox) =
                    make_float2(v0, v1);
            }
        }
    }
}

// ---------------------------------------------------------------------------
extern "C" void kernel_launch(void* const* d_in, const int* in_sizes, int n_in,
                              void* d_out, int out_size) {
    (void)in_sizes; (void)n_in; (void)out_size;
    const float* x  = (const float*)d_in[0];
    const float* gw = (const float*)d_in[1];
    const float* gb = (const float*)d_in[2];
    const float* z  = (const float*)d_in[3];
    const float* w1 = (const float*)d_in[4];
    const float* b1 = (const float*)d_in[5];
    const float* w2 = (const float*)d_in[6];
    const float* b2 = (const float*)d_in[7];
    const float* w3 = (const float*)d_in[8];
    const float* b3 = (const float*)d_in[9];
    float* out = (float*)d_out;

    float *px0, *pa1, *pa2;
    cudaGetSymbolAddress((void**)&px0, g_x0);
    cudaGetSymbolAddress((void**)&pa1, g_a1);
    cudaGetSymbolAddress((void**)&pa2, g_a2);

    // conv1: 128->128, 8x8 -> 16x16 : OHT=16, OCT=32, TOC=4, Q=4, ICC=16, NT=128
    constexpr int S1 = (128 * 10 * 10 + 16 * 32 * 17) * 4;   // 86016
    // conv2: 128->64, 16x16 -> 32x32 : OHT=16, OCT=32, TOC=4, Q=4, ICC=16, NT=256
    constexpr int S2 = (128 * 10 * 18 + 16 * 32 * 17) * 4;   // 126976
    // conv3: 64->3, 32x32 -> 64x64 : OHT=16, OCT=3, TOC=3, Q=2, ICC=64, NT=128
    constexpr int S3 = (64 * 10 * 34 + 64 * 3 * 17) * 4;     // 100096

    cudaFuncSetAttribute(convt_kernel<128, 128, 8, 8, 16, 32, 4, 4, 16, true, 128>,
                         cudaFuncAttributeMaxDynamicSharedMemorySize, S1);
    cudaFuncSetAttribute(convt_kernel<128, 64, 16, 16, 16, 32, 4, 4, 16, true, 256>,
                         cudaFuncAttributeMaxDynamicSharedMemorySize, S2);
    cudaFuncSetAttribute(convt_kernel<64, 3, 32, 32, 16, 3, 3, 2, 64, false, 128>,
                         cudaFuncAttributeMaxDynamicSharedMemorySize, S3);

    lp_kernel<<<B_, 32>>>(x, gw, gb);
    mix_kernel<<<dim3(8192 / 256, B_ / 32), 256>>>(z);

    convt_kernel<128, 128, 8, 8, 16, 32, 4, 4, 16, true, 128>
        <<<dim3(B_, 1, 4), 128, S1>>>(px0, w1, b1, pa1);
    convt_kernel<128, 64, 16, 16, 16, 32, 4, 4, 16, true, 256>
        <<<dim3(B_, 2, 2), 256, S2>>>(pa1, w2, b2, pa2);
    convt_kernel<64, 3, 32, 32, 16, 3, 3, 2, 64, false, 128>
        <<<dim3(B_, 4, 1), 128, S3>>>(pa2, w3, b3, out);
}

// round 3
// speedup vs baseline: 1.8267x; 1.8267x over previous
#include <cuda_runtime.h>
#include <cstdint>

// ---------------------------------------------------------------------------
// MixtureDecoder: soft-tree gating -> leaf mixture -> 3x ConvTranspose2d(4,2,1)
// conv1/conv2 as implicit-GEMM on tensor cores (mma.sync tf32),
// conv3 (OC=3) direct fp32.
// ---------------------------------------------------------------------------

#define B_ 512

__device__ float g_lp[B_ * 32];                   // leaf probs
__device__ float g_x0[B_ * 128 * 8 * 8];          // mixture output (conv1 in)
__device__ float g_a1[(size_t)B_ * 128 * 16 * 16];// conv1 out (relu)
__device__ float g_a2[(size_t)B_ * 64 * 32 * 32]; // conv2 out (relu)

// ---------------- gating + tree leaf probabilities -------------------------
__global__ void lp_kernel(const float* __restrict__ x,
                          const float* __restrict__ gw,
                          const float* __restrict__ gb) {
    int b = blockIdx.x;
    int lane = threadIdx.x;               // 32 threads
    __shared__ float g_sh[31];

    if (lane < 31) {
        float p = gb[lane];
        const float* xb = x + b * 128;
        #pragma unroll 8
        for (int i = 0; i < 128; ++i)
            p += xb[i] * gw[i * 31 + lane];
        g_sh[lane] = 1.0f / (1.0f + expf(-p));
    }
    __syncwarp();

    float lp = 1.0f;
    int prefix = 0;
    #pragma unroll
    for (int d = 1; d <= 5; ++d) {
        float gate = g_sh[(1 << (d - 1)) - 1 + prefix];
        int bit = (lane >> (5 - d)) & 1;
        lp *= bit ? (1.0f - gate) : gate;
        prefix = (prefix << 1) | bit;
    }
    g_lp[b * 32 + lane] = lp;
}

// ---------------- mixture: out0[b,f] = sum_l lp[b,l] * z[f,l] --------------
__global__ __launch_bounds__(256) void mix_kernel(const float* __restrict__ z) {
    int f = blockIdx.x * 256 + threadIdx.x;
    int b0 = blockIdx.y * 32;
    __shared__ float s_lp[32][32];
    for (int i = threadIdx.x; i < 1024; i += 256)
        s_lp[i >> 5][i & 31] = g_lp[b0 * 32 + i];
    __syncthreads();

    float zr[32];
    #pragma unroll
    for (int l4 = 0; l4 < 8; ++l4) {
        float4 v = *reinterpret_cast<const float4*>(z + (size_t)f * 32 + l4 * 4);
        zr[l4 * 4 + 0] = v.x; zr[l4 * 4 + 1] = v.y;
        zr[l4 * 4 + 2] = v.z; zr[l4 * 4 + 3] = v.w;
    }
    #pragma unroll 4
    for (int bi = 0; bi < 32; ++bi) {
        float acc = 0.0f;
        #pragma unroll
        for (int l = 0; l < 32; ++l) acc += zr[l] * s_lp[bi][l];
        g_x0[(size_t)(b0 + bi) * 8192 + f] = acc;
    }
}

// ---------------- tf32 helpers ---------------------------------------------
__device__ __forceinline__ float to_tf32(float v) {
    uint32_t t;
    asm("cvt.rna.tf32.f32 %0, %1;" : "=r"(t) : "f"(v));
    return __uint_as_float(t);
}

__device__ __forceinline__ void mma_tf32(float* c, const uint32_t* a,
                                         uint32_t b0v, uint32_t b1v) {
    asm volatile(
        "mma.sync.aligned.m16n8k8.row.col.f32.tf32.tf32.f32 "
        "{%0,%1,%2,%3}, {%4,%5,%6,%7}, {%8,%9}, {%0,%1,%2,%3};\n"
        : "+f"(c[0]), "+f"(c[1]), "+f"(c[2]), "+f"(c[3])
        : "r"(a[0]), "r"(a[1]), "r"(a[2]), "r"(a[3]), "r"(b0v), "r"(b1v));
}

// ---------------- ConvT(4,2,1) implicit GEMM on tensor cores ----------------
// Per parity (py,px): out quad (jy,jx) = GEMM row; K = 4*IC (taps dy,dx in
// {0,1}^2, ky = 3-py-2*dy, kx = 3-px-2*dx, iy = jy+dy-1+py, ix = jx+dx-1+px).
// s_in: [NB][32 ic][JH+2][JW+2], zero halo, tf32-rounded.
// s_wb: [128 k][72 stride] tf32 weights for (parity, ic-chunk).
template <int JH, int JW, int IC, int OC, int NB, int NCTA,
          int MGROUPS, int NGROUPS, int MT_W, int NT_W, int NWARPS, int MINB>
__global__ __launch_bounds__(NWARPS * 32, MINB) void convt_mma_kernel(
    const float* __restrict__ in, const float* __restrict__ W,
    const float* __restrict__ bias, float* __restrict__ out) {
    constexpr int SR = JW + 2;
    constexpr int CH = (JH + 2) * SR;
    constexpr int ICC = 32;
    constexpr int KCH = 128;                 // k per chunk (= 4*ICC)
    constexpr int NKCH = IC / ICC;
    constexpr int Q = JH * JW;               // quads per batch
    constexpr int IN_CHUNK = NB * ICC * CH;
    constexpr int WBS = 72;                  // conflict-free B stride
    constexpr int NT = NWARPS * 32;
    constexpr int OH = 2 * JH, OW = 2 * JW;

    extern __shared__ float smem[];
    float* s_in = smem;
    float* s_wb = smem + IN_CHUNK;

    const int tid = threadIdx.x;
    const int lane = tid & 31;
    const int w = tid >> 5;
    const int mg = w % MGROUPS;
    const int ng = w / MGROUPS;
    const int kq = lane & 3;                 // k within 4 -> (dy,dx)
    const int dy = kq >> 1, dx = kq & 1;
    const int ln4 = lane >> 2;               // row-in-group / oc-in-group

    const int b0 = blockIdx.x * NB;
    const int oc0 = blockIdx.y * NCTA;
    const int bboff = kq * WBS + ln4;

    for (int p = 0; p < 4; ++p) {
        const int py = p >> 1, px = p & 1;

        // per-thread A offsets (m rows ln4 and ln4+8 of each m-tile)
        int roff[MT_W][2];
        #pragma unroll
        for (int mi = 0; mi < MT_W; ++mi) {
            int m0 = (mg + mi * MGROUPS) * 16;
            int bl = m0 / Q;
            int q0 = m0 % Q;
            #pragma unroll
            for (int h = 0; h < 2; ++h) {
                int q = q0 + ln4 + h * 8;
                int jy = q / JW, jx = q % JW;
                roff[mi][h] = bl * (ICC * CH) + (jy + dy + py) * SR + (jx + dx + px);
            }
        }

        float acc[MT_W][NT_W][4];
        #pragma unroll
        for (int mi = 0; mi < MT_W; ++mi)
            #pragma unroll
            for (int ni = 0; ni < NT_W; ++ni)
                #pragma unroll
                for (int k = 0; k < 4; ++k) acc[mi][ni][k] = 0.0f;

        for (int kc = 0; kc < NKCH; ++kc) {
            __syncthreads();
            // stage input chunk (tf32, zero halo)
            for (int idx = tid; idx < IN_CHUNK; idx += NT) {
                int bl = idx / (ICC * CH);
                int rem = idx % (ICC * CH);
                int icl = rem / CH;
                int rr = rem % CH;
                int ry = rr / SR, cx = rr % SR;
                int iy = ry - 1, ix = cx - 1;
                float v = 0.0f;
                if (iy >= 0 && iy < JH && ix >= 0 && ix < JW)
                    v = in[(((size_t)(b0 + bl) * IC + kc * ICC + icl) * JH + iy) * JW + ix];
                s_in[idx] = to_tf32(v);
            }
            // stage weight chunk for this parity
            const int ky0 = 3 - py, kx0 = 3 - px;
            for (int idx = tid; idx < KCH * NCTA; idx += NT) {
                int n = idx % NCTA;
                int kl = idx / NCTA;
                int icl = kl >> 2;
                int ddy = (kl >> 1) & 1, ddx = kl & 1;
                int ky = ky0 - 2 * ddy, kx = kx0 - 2 * ddx;
                float v = W[(((size_t)(kc * ICC + icl) * OC) + oc0 + n) * 16 + ky * 4 + kx];
                s_wb[kl * WBS + n] = to_tf32(v);
            }
            __syncthreads();

            #pragma unroll 4
            for (int s = 0; s < 16; ++s) {
                uint32_t a[MT_W][4];
                const float* sa = s_in + s * 2 * CH;
                #pragma unroll
                for (int mi = 0; mi < MT_W; ++mi) {
                    a[mi][0] = __float_as_uint(sa[roff[mi][0]]);
                    a[mi][1] = __float_as_uint(sa[roff[mi][1]]);
                    a[mi][2] = __float_as_uint(sa[roff[mi][0] + CH]);
                    a[mi][3] = __float_as_uint(sa[roff[mi][1] + CH]);
                }
                const float* sb = s_wb + s * 8 * WBS + bboff;
                #pragma unroll
                for (int ni = 0; ni < NT_W; ++ni) {
                    int n0 = (ng * NT_W + ni) * 8;
                    uint32_t bb0 = __float_as_uint(sb[n0]);
                    uint32_t bb1 = __float_as_uint(sb[n0 + 4 * WBS]);
                    #pragma unroll
                    for (int mi = 0; mi < MT_W; ++mi)
                        mma_tf32(acc[mi][ni], a[mi], bb0, bb1);
                }
            }
        }

        // epilogue: bias + relu, NCHW scatter
        #pragma unroll
        for (int mi = 0; mi < MT_W; ++mi) {
            int m0 = (mg + mi * MGROUPS) * 16;
            int bl = m0 / Q;
            int q0 = m0 % Q;
            #pragma unroll
            for (int ni = 0; ni < NT_W; ++ni) {
                int oc = oc0 + (ng * NT_W + ni) * 8 + 2 * kq;
                float bv0 = bias[oc], bv1 = bias[oc + 1];
                #pragma unroll
                for (int h = 0; h < 2; ++h) {
                    int q = q0 + ln4 + h * 8;
                    int jy = q / JW, jx = q % JW;
                    int oy = 2 * jy + py, ox = 2 * jx + px;
                    size_t o = (((size_t)(b0 + bl) * OC + oc) * OH + oy) * OW + ox;
                    float v0 = fmaxf(acc[mi][ni][2 * h + 0] + bv0, 0.0f);
                    float v1 = fmaxf(acc[mi][ni][2 * h + 1] + bv1, 0.0f);
                    out[o] = v0;
                    out[o + (size_t)OH * OW] = v1;
                }
            }
        }
    }
}

// ---------------- ConvTranspose2d direct fp32 (conv3 only) -----------------
template <int IC, int OC, int IH, int IW, int OHT, int OCT, int TOC, int Q,
          int ICC, bool RELU, int NT>
__global__ __launch_bounds__(NT) void convt_kernel(
    const float* __restrict__ in, const float* __restrict__ W,
    const float* __restrict__ bias, float* __restrict__ out) {
    constexpr int OH = 2 * IH, OW = 2 * IW;
    constexpr int NQY = OHT / 2, NQX = OW / 2, XG = NQX / Q;
    constexpr int SROWS = NQY + 2, SCOLS = IW + 2;
    constexpr int IN_ELE = IC * SROWS * SCOLS;
    constexpr int WSTR = 17;

    extern __shared__ float smem[];
    float* s_in = smem;
    float* s_w = smem + IN_ELE;

    const int b = blockIdx.x;
    const int jy0 = blockIdx.y * NQY;
    const int oc0 = blockIdx.z * OCT;

    const int tid = threadIdx.x;
    const int sp = tid % (NQY * XG);
    const int ocg = tid / (NQY * XG);
    const int qxg = sp % XG;
    const int qy = sp / XG;
    const int qx0 = qxg * Q;

    const float* inb = in + (size_t)b * IC * IH * IW;
    for (int idx = tid; idx < IN_ELE; idx += NT) {
        int ic = idx / (SROWS * SCOLS);
        int r = idx % (SROWS * SCOLS);
        int ry = r / SCOLS, cx = r % SCOLS;
        int iy = jy0 - 1 + ry, ix = cx - 1;
        float v = 0.0f;
        if (iy >= 0 && iy < IH && ix >= 0 && ix < IW)
            v = inb[(ic * IH + iy) * IW + ix];
        s_in[idx] = v;
    }

    float acc[TOC][Q][4];
    #pragma unroll
    for (int t = 0; t < TOC; ++t)
        #pragma unroll
        for (int q = 0; q < Q; ++q)
            #pragma unroll
            for (int k = 0; k < 4; ++k) acc[t][q][k] = 0.0f;

    for (int ic0 = 0; ic0 < IC; ic0 += ICC) {
        __syncthreads();
        for (int idx = tid; idx < ICC * OCT * 16; idx += NT) {
            int k = idx & 15;
            int ol = (idx >> 4) % OCT;
            int icl = idx / (16 * OCT);
            s_w[(icl * OCT + ol) * WSTR + k] =
                W[((size_t)(ic0 + icl) * OC + oc0 + ol) * 16 + k];
        }
        __syncthreads();

        for (int icl = 0; icl < ICC; ++icl) {
            const float* si =
                s_in + (ic0 + icl) * (SROWS * SCOLS) + qy * SCOLS + qx0;
            float iv[3][Q + 2];
            #pragma unroll
            for (int r = 0; r < 3; ++r)
                #pragma unroll
                for (int c = 0; c < Q + 2; ++c) iv[r][c] = si[r * SCOLS + c];

            #pragma unroll
            for (int t = 0; t < TOC; ++t) {
                const float* wp = s_w + (icl * OCT + ocg * TOC + t) * WSTR;
                float w[16];
                #pragma unroll
                for (int k = 0; k < 16; ++k) w[k] = wp[k];
                #pragma unroll
                for (int q = 0; q < Q; ++q) {
                    float* a = acc[t][q];
                    a[0] += iv[0][q] * w[15];     a[0] += iv[0][q + 1] * w[13];
                    a[0] += iv[1][q] * w[7];      a[0] += iv[1][q + 1] * w[5];
                    a[1] += iv[0][q + 1] * w[14]; a[1] += iv[0][q + 2] * w[12];
                    a[1] += iv[1][q + 1] * w[6];  a[1] += iv[1][q + 2] * w[4];
                    a[2] += iv[1][q] * w[11];     a[2] += iv[1][q + 1] * w[9];
                    a[2] += iv[2][q] * w[3];      a[2] += iv[2][q + 1] * w[1];
                    a[3] += iv[1][q + 1] * w[10]; a[3] += iv[1][q + 2] * w[8];
                    a[3] += iv[2][q + 1] * w[2];  a[3] += iv[2][q + 2] * w[0];
                }
            }
        }
    }

    float* outb = out + (size_t)b * OC * OH * OW;
    #pragma unroll
    for (int t = 0; t < TOC; ++t) {
        int oc = oc0 + ocg * TOC + t;
        float bv = bias[oc];
        #pragma unroll
        for (int q = 0; q < Q; ++q) {
            int ox = 2 * (qx0 + q);
            #pragma unroll
            for (int py = 0; py < 2; ++py) {
                int oy = 2 * (jy0 + qy) + py;
                float v0 = acc[t][q][py * 2 + 0] + bv;
                float v1 = acc[t][q][py * 2 + 1] + bv;
                if (RELU) { v0 = fmaxf(v0, 0.0f); v1 = fmaxf(v1, 0.0f); }
                *reinterpret_cast<float2*>(outb + ((size_t)oc * OH + oy) * OW + ox) =
                    make_float2(v0, v1);
            }
        }
    }
}

// ---------------------------------------------------------------------------
extern "C" void kernel_launch(void* const* d_in, const int* in_sizes, int n_in,
                              void* d_out, int out_size) {
    (void)in_sizes; (void)n_in; (void)out_size;
    const float* x  = (const float*)d_in[0];
    const float* gw = (const float*)d_in[1];
    const float* gb = (const float*)d_in[2];
    const float* z  = (const float*)d_in[3];
    const float* w1 = (const float*)d_in[4];
    const float* b1 = (const float*)d_in[5];
    const float* w2 = (const float*)d_in[6];
    const float* b2 = (const float*)d_in[7];
    const float* w3 = (const float*)d_in[8];
    const float* b3 = (const float*)d_in[9];
    float* out = (float*)d_out;

    float *px0, *pa1, *pa2;
    cudaGetSymbolAddress((void**)&px0, g_x0);
    cudaGetSymbolAddress((void**)&pa1, g_a1);
    cudaGetSymbolAddress((void**)&pa2, g_a2);

    // conv1 (tensor): JH=8, NB=4, NCTA=64 (grid.y=2), 16 warps, MT_W=2, NT_W=4
    constexpr int S1 = (4 * 32 * 100 + 128 * 72) * 4;   // 88064
    // conv2 (tensor): JH=16, NB=2, NCTA=64, 16 warps, MT_W=4, NT_W=4
    constexpr int S2 = (2 * 32 * 324 + 128 * 72) * 4;   // 119808
    // conv3 (fp32 direct): 64->3
    constexpr int S3 = (64 * 10 * 34 + 64 * 3 * 17) * 4; // 100096

    auto k1 = convt_mma_kernel<8, 8, 128, 128, 4, 64, 8, 2, 2, 4, 16, 2>;
    auto k2 = convt_mma_kernel<16, 16, 128, 64, 2, 64, 8, 2, 4, 4, 16, 1>;
    auto k3 = convt_kernel<64, 3, 32, 32, 16, 3, 3, 2, 64, false, 128>;

    cudaFuncSetAttribute(k1, cudaFuncAttributeMaxDynamicSharedMemorySize, S1);
    cudaFuncSetAttribute(k2, cudaFuncAttributeMaxDynamicSharedMemorySize, S2);
    cudaFuncSetAttribute(k3, cudaFuncAttributeMaxDynamicSharedMemorySize, S3);

    lp_kernel<<<B_, 32>>>(x, gw, gb);
    mix_kernel<<<dim3(8192 / 256, B_ / 32), 256>>>(z);

    k1<<<dim3(B_ / 4, 2), 512, S1>>>(px0, w1, b1, pa1);
    k2<<<dim3(B_ / 2, 1), 512, S2>>>(pa1, w2, b2, pa2);
    k3<<<dim3(B_, 4, 1), 128, S3>>>(pa2, w3, b3, out);
}

// round 4
// speedup vs baseline: 2.0068x; 1.0986x over previous
#include <cuda_runtime.h>
#include <cstdint>

// ---------------------------------------------------------------------------
// MixtureDecoder: soft-tree gating -> leaf mixture -> 3x ConvTranspose2d(4,2,1)
// conv1/conv2: implicit-GEMM tensor cores (mma.sync tf32), input fully
// resident in smem (staged once per CTA). conv3 (OC=3) direct fp32.
// ---------------------------------------------------------------------------

#define B_ 512

__device__ float g_lp[B_ * 32];                   // leaf probs
__device__ float g_x0[B_ * 128 * 8 * 8];          // mixture output (conv1 in)
__device__ float g_a1[(size_t)B_ * 128 * 16 * 16];// conv1 out (relu)
__device__ float g_a2[(size_t)B_ * 64 * 32 * 32]; // conv2 out (relu)

// ---------------- gating + tree leaf probabilities -------------------------
__global__ void lp_kernel(const float* __restrict__ x,
                          const float* __restrict__ gw,
                          const float* __restrict__ gb) {
    int b = blockIdx.x;
    int lane = threadIdx.x;               // 32 threads
    __shared__ float g_sh[31];

    if (lane < 31) {
        float p = gb[lane];
        const float* xb = x + b * 128;
        #pragma unroll 8
        for (int i = 0; i < 128; ++i)
            p += xb[i] * gw[i * 31 + lane];
        g_sh[lane] = 1.0f / (1.0f + expf(-p));
    }
    __syncwarp();

    float lp = 1.0f;
    int prefix = 0;
    #pragma unroll
    for (int d = 1; d <= 5; ++d) {
        float gate = g_sh[(1 << (d - 1)) - 1 + prefix];
        int bit = (lane >> (5 - d)) & 1;
        lp *= bit ? (1.0f - gate) : gate;
        prefix = (prefix << 1) | bit;
    }
    g_lp[b * 32 + lane] = lp;
}

// ---------------- mixture: out0[b,f] = sum_l lp[b,l] * z[f,l] --------------
__global__ __launch_bounds__(256) void mix_kernel(const float* __restrict__ z) {
    int f = blockIdx.x * 256 + threadIdx.x;
    int b0 = blockIdx.y * 32;
    __shared__ float s_lp[32][32];
    for (int i = threadIdx.x; i < 1024; i += 256)
        s_lp[i >> 5][i & 31] = g_lp[b0 * 32 + i];
    __syncthreads();

    float zr[32];
    #pragma unroll
    for (int l4 = 0; l4 < 8; ++l4) {
        float4 v = *reinterpret_cast<const float4*>(z + (size_t)f * 32 + l4 * 4);
        zr[l4 * 4 + 0] = v.x; zr[l4 * 4 + 1] = v.y;
        zr[l4 * 4 + 2] = v.z; zr[l4 * 4 + 3] = v.w;
    }
    #pragma unroll 4
    for (int bi = 0; bi < 32; ++bi) {
        float acc = 0.0f;
        #pragma unroll
        for (int l = 0; l < 32; ++l) acc += zr[l] * s_lp[bi][l];
        g_x0[(size_t)(b0 + bi) * 8192 + f] = acc;
    }
}

// ---------------- tf32 helpers ---------------------------------------------
__device__ __forceinline__ float to_tf32(float v) {
    uint32_t t;
    asm("cvt.rna.tf32.f32 %0, %1;" : "=r"(t) : "f"(v));
    return __uint_as_float(t);
}

__device__ __forceinline__ void mma_tf32(float* c, const uint32_t* a,
                                         uint32_t b0v, uint32_t b1v) {
    asm volatile(
        "mma.sync.aligned.m16n8k8.row.col.f32.tf32.tf32.f32 "
        "{%0,%1,%2,%3}, {%4,%5,%6,%7}, {%8,%9}, {%0,%1,%2,%3};\n"
        : "+f"(c[0]), "+f"(c[1]), "+f"(c[2]), "+f"(c[3])
        : "r"(a[0]), "r"(a[1]), "r"(a[2]), "r"(a[3]), "r"(b0v), "r"(b1v));
}

// ---------------- ConvT(4,2,1) implicit GEMM, resident-input version -------
// Per parity (py,px): out quad (jy,jx) = GEMM row; K = 4*IC (taps dy,dx in
// {0,1}^2, ky = 3-py-2*dy, kx = 3-px-2*dx, iy = jy+dy-1+py, ix = jx+dx-1+px).
// s_in: [NB][IC][JH+2][JW+2], zero halo, tf32 — staged ONCE per CTA.
// s_wb: [128 k][WBS] tf32 weights for (parity, ic-chunk), restaged per chunk.
template <int JH, int JW, int IC, int OC, int NB,
          int MGROUPS, int NGROUPS, int MT_W, int NT_W, int NWARPS, int WBS>
__global__ __launch_bounds__(NWARPS * 32) void convt_mma_kernel(
    const float* __restrict__ in, const float* __restrict__ W,
    const float* __restrict__ bias, float* __restrict__ out) {
    constexpr int SR = JW + 2;
    constexpr int CH = (JH + 2) * SR;
    constexpr int ICC = 32;
    constexpr int KCH = 128;                 // k per chunk (= 4*ICC)
    constexpr int NKCH = IC / ICC;
    constexpr int Q = JH * JW;               // quads per batch
    constexpr int IN_ELE = NB * IC * CH;
    constexpr int NT = NWARPS * 32;
    constexpr int OH = 2 * JH, OW = 2 * JW;

    extern __shared__ float smem[];
    float* s_in = smem;
    float* s_wb = smem + IN_ELE;

    const int tid = threadIdx.x;
    const int lane = tid & 31;
    const int w = tid >> 5;
    const int mg = w % MGROUPS;
    const int ng = w / MGROUPS;
    const int kq = lane & 3;                 // k within 4 -> (dy,dx)
    const int dy = kq >> 1, dx = kq & 1;
    const int ln4 = lane >> 2;               // row-in-group / oc-in-group

    const int b0 = blockIdx.x * NB;
    const int bboff = kq * WBS + ln4;

    // ---- stage full input (all channels), tf32, zero halo — ONCE ----
    for (int idx = tid; idx < IN_ELE; idx += NT) {
        int bl = idx / (IC * CH);
        int rem = idx % (IC * CH);
        int ic = rem / CH;
        int rr = rem % CH;
        int ry = rr / SR, cx = rr % SR;
        int iy = ry - 1, ix = cx - 1;
        float v = 0.0f;
        if (iy >= 0 && iy < JH && ix >= 0 && ix < JW)
            v = in[(((size_t)(b0 + bl) * IC + ic) * JH + iy) * JW + ix];
        s_in[idx] = to_tf32(v);
    }

    for (int p = 0; p < 4; ++p) {
        const int py = p >> 1, px = p & 1;

        // per-thread A offsets (m rows ln4 and ln4+8 of each m-tile)
        int roff[MT_W][2];
        #pragma unroll
        for (int mi = 0; mi < MT_W; ++mi) {
            int m0 = (mg + mi * MGROUPS) * 16;
            int bl = m0 / Q;
            int q0 = m0 % Q;
            #pragma unroll
            for (int h = 0; h < 2; ++h) {
                int q = q0 + ln4 + h * 8;
                int jy = q / JW, jx = q % JW;
                roff[mi][h] = bl * (IC * CH) + (jy + dy + py) * SR + (jx + dx + px);
            }
        }

        float acc[MT_W][NT_W][4];
        #pragma unroll
        for (int mi = 0; mi < MT_W; ++mi)
            #pragma unroll
            for (int ni = 0; ni < NT_W; ++ni)
                #pragma unroll
                for (int k = 0; k < 4; ++k) acc[mi][ni][k] = 0.0f;

        for (int kc = 0; kc < NKCH; ++kc) {
            __syncthreads();   // s_wb reuse safe; also covers input staging
            // stage weight chunk for this parity (L2-hot, small)
            const int ky0 = 3 - py, kx0 = 3 - px;
            for (int idx = tid; idx < KCH * OC; idx += NT) {
                int n = idx % OC;
                int kl = idx / OC;
                int icl = kl >> 2;
                int ddy = (kl >> 1) & 1, ddx = kl & 1;
                int ky = ky0 - 2 * ddy, kx = kx0 - 2 * ddx;
                float v = W[(((size_t)(kc * ICC + icl) * OC) + n) * 16 + ky * 4 + kx];
                s_wb[kl * WBS + n] = to_tf32(v);
            }
            __syncthreads();

            #pragma unroll 4
            for (int s = 0; s < 16; ++s) {
                uint32_t a[MT_W][4];
                const float* sa = s_in + (kc * ICC + s * 2) * CH;
                #pragma unroll
                for (int mi = 0; mi < MT_W; ++mi) {
                    a[mi][0] = __float_as_uint(sa[roff[mi][0]]);
                    a[mi][1] = __float_as_uint(sa[roff[mi][1]]);
                    a[mi][2] = __float_as_uint(sa[roff[mi][0] + CH]);
                    a[mi][3] = __float_as_uint(sa[roff[mi][1] + CH]);
                }
                const float* sb = s_wb + s * 8 * WBS + bboff;
                #pragma unroll
                for (int ni = 0; ni < NT_W; ++ni) {
                    int n0 = (ng * NT_W + ni) * 8;
                    uint32_t bb0 = __float_as_uint(sb[n0]);
                    uint32_t bb1 = __float_as_uint(sb[n0 + 4 * WBS]);
                    #pragma unroll
                    for (int mi = 0; mi < MT_W; ++mi)
                        mma_tf32(acc[mi][ni], a[mi], bb0, bb1);
                }
            }
        }

        // epilogue: bias + relu, NCHW scatter
        #pragma unroll
        for (int mi = 0; mi < MT_W; ++mi) {
            int m0 = (mg + mi * MGROUPS) * 16;
            int bl = m0 / Q;
            int q0 = m0 % Q;
            #pragma unroll
            for (int ni = 0; ni < NT_W; ++ni) {
                int oc = (ng * NT_W + ni) * 8 + 2 * kq;
                float bv0 = bias[oc], bv1 = bias[oc + 1];
                #pragma unroll
                for (int h = 0; h < 2; ++h) {
                    int q = q0 + ln4 + h * 8;
                    int jy = q / JW, jx = q % JW;
                    int oy = 2 * jy + py, ox = 2 * jx + px;
                    size_t o = (((size_t)(b0 + bl) * OC + oc) * OH + oy) * OW + ox;
                    float v0 = fmaxf(acc[mi][ni][2 * h + 0] + bv0, 0.0f);
                    float v1 = fmaxf(acc[mi][ni][2 * h + 1] + bv1, 0.0f);
                    out[o] = v0;
                    out[o + (size_t)OH * OW] = v1;
                }
            }
        }
    }
}

// ---------------- ConvTranspose2d direct fp32 (conv3 only) -----------------
template <int IC, int OC, int IH, int IW, int OHT, int OCT, int TOC, int Q,
          int ICC, bool RELU, int NT>
__global__ __launch_bounds__(NT) void convt_kernel(
    const float* __restrict__ in, const float* __restrict__ W,
    const float* __restrict__ bias, float* __restrict__ out) {
    constexpr int OH = 2 * IH, OW = 2 * IW;
    constexpr int NQY = OHT / 2, NQX = OW / 2, XG = NQX / Q;
    constexpr int SROWS = NQY + 2, SCOLS = IW + 2;
    constexpr int IN_ELE = IC * SROWS * SCOLS;
    constexpr int WSTR = 17;

    extern __shared__ float smem[];
    float* s_in = smem;
    float* s_w = smem + IN_ELE;

    const int b = blockIdx.x;
    const int jy0 = blockIdx.y * NQY;
    const int oc0 = blockIdx.z * OCT;

    const int tid = threadIdx.x;
    const int sp = tid % (NQY * XG);
    const int ocg = tid / (NQY * XG);
    const int qxg = sp % XG;
    const int qy = sp / XG;
    const int qx0 = qxg * Q;

    const float* inb = in + (size_t)b * IC * IH * IW;
    for (int idx = tid; idx < IN_ELE; idx += NT) {
        int ic = idx / (SROWS * SCOLS);
        int r = idx % (SROWS * SCOLS);
        int ry = r / SCOLS, cx = r % SCOLS;
        int iy = jy0 - 1 + ry, ix = cx - 1;
        float v = 0.0f;
        if (iy >= 0 && iy < IH && ix >= 0 && ix < IW)
            v = inb[(ic * IH + iy) * IW + ix];
        s_in[idx] = v;
    }

    float acc[TOC][Q][4];
    #pragma unroll
    for (int t = 0; t < TOC; ++t)
        #pragma unroll
        for (int q = 0; q < Q; ++q)
            #pragma unroll
            for (int k = 0; k < 4; ++k) acc[t][q][k] = 0.0f;

    for (int ic0 = 0; ic0 < IC; ic0 += ICC) {
        __syncthreads();
        for (int idx = tid; idx < ICC * OCT * 16; idx += NT) {
            int k = idx & 15;
            int ol = (idx >> 4) % OCT;
            int icl = idx / (16 * OCT);
            s_w[(icl * OCT + ol) * WSTR + k] =
                W[((size_t)(ic0 + icl) * OC + oc0 + ol) * 16 + k];
        }
        __syncthreads();

        for (int icl = 0; icl < ICC; ++icl) {
            const float* si =
                s_in + (ic0 + icl) * (SROWS * SCOLS) + qy * SCOLS + qx0;
            float iv[3][Q + 2];
            #pragma unroll
            for (int r = 0; r < 3; ++r)
                #pragma unroll
                for (int c = 0; c < Q + 2; ++c) iv[r][c] = si[r * SCOLS + c];

            #pragma unroll
            for (int t = 0; t < TOC; ++t) {
                const float* wp = s_w + (icl * OCT + ocg * TOC + t) * WSTR;
                float w[16];
                #pragma unroll
                for (int k = 0; k < 16; ++k) w[k] = wp[k];
                #pragma unroll
                for (int q = 0; q < Q; ++q) {
                    float* a = acc[t][q];
                    a[0] += iv[0][q] * w[15];     a[0] += iv[0][q + 1] * w[13];
                    a[0] += iv[1][q] * w[7];      a[0] += iv[1][q + 1] * w[5];
                    a[1] += iv[0][q + 1] * w[14]; a[1] += iv[0][q + 2] * w[12];
                    a[1] += iv[1][q + 1] * w[6];  a[1] += iv[1][q + 2] * w[4];
                    a[2] += iv[1][q] * w[11];     a[2] += iv[1][q + 1] * w[9];
                    a[2] += iv[2][q] * w[3];      a[2] += iv[2][q + 1] * w[1];
                    a[3] += iv[1][q + 1] * w[10]; a[3] += iv[1][q + 2] * w[8];
                    a[3] += iv[2][q + 1] * w[2];  a[3] += iv[2][q + 2] * w[0];
                }
            }
        }
    }

    float* outb = out + (size_t)b * OC * OH * OW;
    #pragma unroll
    for (int t = 0; t < TOC; ++t) {
        int oc = oc0 + ocg * TOC + t;
        float bv = bias[oc];
        #pragma unroll
        for (int q = 0; q < Q; ++q) {
            int ox = 2 * (qx0 + q);
            #pragma unroll
            for (int py = 0; py < 2; ++py) {
                int oy = 2 * (jy0 + qy) + py;
                float v0 = acc[t][q][py * 2 + 0] + bv;
                float v1 = acc[t][q][py * 2 + 1] + bv;
                if (RELU) { v0 = fmaxf(v0, 0.0f); v1 = fmaxf(v1, 0.0f); }
                *reinterpret_cast<float2*>(outb + ((size_t)oc * OH + oy) * OW + ox) =
                    make_float2(v0, v1);
            }
        }
    }
}

// ---------------------------------------------------------------------------
extern "C" void kernel_launch(void* const* d_in, const int* in_sizes, int n_in,
                              void* d_out, int out_size) {
    (void)in_sizes; (void)n_in; (void)out_size;
    const float* x  = (const float*)d_in[0];
    const float* gw = (const float*)d_in[1];
    const float* gb = (const float*)d_in[2];
    const float* z  = (const float*)d_in[3];
    const float* w1 = (const float*)d_in[4];
    const float* b1 = (const float*)d_in[5];
    const float* w2 = (const float*)d_in[6];
    const float* b2 = (const float*)d_in[7];
    const float* w3 = (const float*)d_in[8];
    const float* b3 = (const float*)d_in[9];
    float* out = (float*)d_out;

    float *px0, *pa1, *pa2;
    cudaGetSymbolAddress((void**)&px0, g_x0);
    cudaGetSymbolAddress((void**)&pa1, g_a1);
    cudaGetSymbolAddress((void**)&pa2, g_a2);

    // conv1: JH=8, NB=2, full OC=128, 16 warps, MT_W=2, NT_W=4, WBS=136
    constexpr int S1 = (2 * 128 * 100 + 128 * 136) * 4;   // 172,032
    // conv2: JH=16, NB=1, OC=64, 16 warps, MT_W=2, NT_W=4, WBS=72
    constexpr int S2 = (1 * 128 * 324 + 128 * 72) * 4;    // 202,752
    // conv3 (fp32 direct): 64->3
    constexpr int S3 = (64 * 10 * 34 + 64 * 3 * 17) * 4;  // 100,096

    auto k1 = convt_mma_kernel<8, 8, 128, 128, 2, 4, 4, 2, 4, 16, 136>;
    auto k2 = convt_mma_kernel<16, 16, 128, 64, 1, 8, 2, 2, 4, 16, 72>;
    auto k3 = convt_kernel<64, 3, 32, 32, 16, 3, 3, 2, 64, false, 128>;

    cudaFuncSetAttribute(k1, cudaFuncAttributeMaxDynamicSharedMemorySize, S1);
    cudaFuncSetAttribute(k2, cudaFuncAttributeMaxDynamicSharedMemorySize, S2);
    cudaFuncSetAttribute(k3, cudaFuncAttributeMaxDynamicSharedMemorySize, S3);

    lp_kernel<<<B_, 32>>>(x, gw, gb);
    mix_kernel<<<dim3(8192 / 256, B_ / 32), 256>>>(z);

    k1<<<dim3(B_ / 2), 512, S1>>>(px0, w1, b1, pa1);
    k2<<<dim3(B_ / 1), 512, S2>>>(pa1, w2, b2, pa2);
    k3<<<dim3(B_, 4, 1), 128, S3>>>(pa2, w3, b3, out);
}

// round 5
// speedup vs baseline: 2.1861x; 1.0893x over previous
#include <cuda_runtime.h>
#include <cstdint>

// ---------------------------------------------------------------------------
// MixtureDecoder: soft-tree gating -> leaf mixture -> 3x ConvTranspose2d(4,2,1)
// conv1/conv2: implicit-GEMM tensor cores (mma.sync tf32), resident input,
// pre-transformed weights staged via double-buffered cp.async.
// conv3 (OC=3) direct fp32.
// ---------------------------------------------------------------------------

#define B_ 512

__device__ float g_lp[B_ * 32];                   // leaf probs
__device__ float g_x0[B_ * 128 * 8 * 8];          // mixture output (conv1 in)
__device__ float g_a1[(size_t)B_ * 128 * 16 * 16];// conv1 out (relu)
__device__ float g_a2[(size_t)B_ * 64 * 32 * 32]; // conv2 out (relu)
__device__ float g_w1t[4 * 512 * 128];            // conv1 W: [p][k][oc] tf32
__device__ float g_w2t[4 * 512 * 64];             // conv2 W: [p][k][oc] tf32

// ---------------- gating + tree leaf probabilities -------------------------
__global__ void lp_kernel(const float* __restrict__ x,
                          const float* __restrict__ gw,
                          const float* __restrict__ gb) {
    int b = blockIdx.x;
    int lane = threadIdx.x;               // 32 threads
    __shared__ float g_sh[31];

    if (lane < 31) {
        float p = gb[lane];
        const float* xb = x + b * 128;
        #pragma unroll 8
        for (int i = 0; i < 128; ++i)
            p += xb[i] * gw[i * 31 + lane];
        g_sh[lane] = 1.0f / (1.0f + expf(-p));
    }
    __syncwarp();

    float lp = 1.0f;
    int prefix = 0;
    #pragma unroll
    for (int d = 1; d <= 5; ++d) {
        float gate = g_sh[(1 << (d - 1)) - 1 + prefix];
        int bit = (lane >> (5 - d)) & 1;
        lp *= bit ? (1.0f - gate) : gate;
        prefix = (prefix << 1) | bit;
    }
    g_lp[b * 32 + lane] = lp;
}

// ---------------- mixture: out0[b,f] = sum_l lp[b,l] * z[f,l] --------------
__global__ __launch_bounds__(256) void mix_kernel(const float* __restrict__ z) {
    int f = blockIdx.x * 256 + threadIdx.x;
    int b0 = blockIdx.y * 32;
    __shared__ float s_lp[32][32];
    for (int i = threadIdx.x; i < 1024; i += 256)
        s_lp[i >> 5][i & 31] = g_lp[b0 * 32 + i];
    __syncthreads();

    float zr[32];
    #pragma unroll
    for (int l4 = 0; l4 < 8; ++l4) {
        float4 v = *reinterpret_cast<const float4*>(z + (size_t)f * 32 + l4 * 4);
        zr[l4 * 4 + 0] = v.x; zr[l4 * 4 + 1] = v.y;
        zr[l4 * 4 + 2] = v.z; zr[l4 * 4 + 3] = v.w;
    }
    #pragma unroll 4
    for (int bi = 0; bi < 32; ++bi) {
        float acc = 0.0f;
        #pragma unroll
        for (int l = 0; l < 32; ++l) acc += zr[l] * s_lp[bi][l];
        g_x0[(size_t)(b0 + bi) * 8192 + f] = acc;
    }
}

// ---------------- tf32 helpers ---------------------------------------------
__device__ __forceinline__ float to_tf32(float v) {
    uint32_t t;
    asm("cvt.rna.tf32.f32 %0, %1;" : "=r"(t) : "f"(v));
    return __uint_as_float(t);
}

__device__ __forceinline__ void mma_tf32(float* c, const uint32_t* a,
                                         uint32_t b0v, uint32_t b1v) {
    asm volatile(
        "mma.sync.aligned.m16n8k8.row.col.f32.tf32.tf32.f32 "
        "{%0,%1,%2,%3}, {%4,%5,%6,%7}, {%8,%9}, {%0,%1,%2,%3};\n"
        : "+f"(c[0]), "+f"(c[1]), "+f"(c[2]), "+f"(c[3])
        : "r"(a[0]), "r"(a[1]), "r"(a[2]), "r"(a[3]), "r"(b0v), "r"(b1v));
}

__device__ __forceinline__ void cp_async16(uint32_t dst, const float* src) {
    asm volatile("cp.async.cg.shared.global [%0], [%1], 16;"
                 :: "r"(dst), "l"(src));
}

// ---------------- weight pre-transform: W[ic][oc][ky][kx] -> [p][k][oc] ----
// k = ic*4 + tap, tap=(ddy*2+ddx); ky = 3-py-2*ddy, kx = 3-px-2*ddx.
template <int IC, int OC>
__global__ __launch_bounds__(256) void wprep_kernel(const float* __restrict__ W,
                                                    float* __restrict__ Wt) {
    int idx = blockIdx.x * 256 + threadIdx.x;
    constexpr int K = 4 * IC;
    if (idx >= 4 * K * OC) return;
    int n = idx % OC;
    int k = (idx / OC) % K;
    int p = idx / (OC * K);
    int ic = k >> 2;
    int ddy = (k >> 1) & 1, ddx = k & 1;
    int py = p >> 1, px = p & 1;
    int ky = 3 - py - 2 * ddy, kx = 3 - px - 2 * ddx;
    Wt[idx] = to_tf32(W[((size_t)ic * OC + n) * 16 + ky * 4 + kx]);
}

// ---------------- ConvT(4,2,1) implicit GEMM, async-weights version --------
// Per parity (py,px): out quad (jy,jx) = GEMM row; K = 4*IC.
// s_in: [NB][IC][JH+2][JW+2], zero halo, tf32 — staged ONCE per CTA.
// s_wb: double-buffered [KCH=64 k][WBS] chunks from pre-transformed Wt,
//       filled by cp.async overlapping the MMA of the previous chunk.
template <int JH, int JW, int IC, int OC, int NB,
          int MGROUPS, int NGROUPS, int MT_W, int NT_W, int NWARPS, int WBS>
__global__ __launch_bounds__(NWARPS * 32) void convt_mma_kernel(
    const float* __restrict__ in, const float* __restrict__ Wt,
    const float* __restrict__ bias, float* __restrict__ out) {
    constexpr int SR = JW + 2;
    constexpr int CH = (JH + 2) * SR;
    constexpr int KCH = 64;                  // k rows per chunk
    constexpr int KTOT = 4 * IC;
    constexpr int NKCH = KTOT / KCH;         // 8 for IC=128
    constexpr int Q = JH * JW;               // quads per batch
    constexpr int IN_ELE = NB * IC * CH;
    constexpr int NT = NWARPS * 32;
    constexpr int OH = 2 * JH, OW = 2 * JW;
    constexpr int PIECES = KCH * OC / 4;     // 16B pieces per chunk

    extern __shared__ float smem[];
    float* s_in = smem;
    float* s_wb[2] = {smem + IN_ELE, smem + IN_ELE + KCH * WBS};
    uint32_t wb_u32[2] = {(uint32_t)__cvta_generic_to_shared(s_wb[0]),
                          (uint32_t)__cvta_generic_to_shared(s_wb[1])};

    const int tid = threadIdx.x;
    const int lane = tid & 31;
    const int w = tid >> 5;
    const int mg = w % MGROUPS;
    const int ng = w / MGROUPS;
    const int kq = lane & 3;                 // k within 4 -> (dy,dx)
    const int dy = kq >> 1, dx = kq & 1;
    const int ln4 = lane >> 2;               // row-in-group / oc-in-group

    const int b0 = blockIdx.x * NB;
    const int bboff = kq * WBS + ln4;

    // ---- stage full input (all channels), tf32, zero halo — ONCE ----
    for (int idx = tid; idx < IN_ELE; idx += NT) {
        int bl = idx / (IC * CH);
        int rem = idx % (IC * CH);
        int ic = rem / CH;
        int rr = rem % CH;
        int ry = rr / SR, cx = rr % SR;
        int iy = ry - 1, ix = cx - 1;
        float v = 0.0f;
        if (iy >= 0 && iy < JH && ix >= 0 && ix < JW)
            v = in[(((size_t)(b0 + bl) * IC + ic) * JH + iy) * JW + ix];
        s_in[idx] = to_tf32(v);
    }

    for (int p = 0; p < 4; ++p) {
        const int py = p >> 1, px = p & 1;
        const float* wsrc = Wt + (size_t)p * KTOT * OC;

        // per-thread A offsets (m rows ln4 and ln4+8 of each m-tile)
        int roff[MT_W][2];
        #pragma unroll
        for (int mi = 0; mi < MT_W; ++mi) {
            int m0 = (mg + mi * MGROUPS) * 16;
            int bl = m0 / Q;
            int q0 = m0 % Q;
            #pragma unroll
            for (int h = 0; h < 2; ++h) {
                int q = q0 + ln4 + h * 8;
                int jy = q / JW, jx = q % JW;
                roff[mi][h] = bl * (IC * CH) + (jy + dy + py) * SR + (jx + dx + px);
            }
        }

        float acc[MT_W][NT_W][4];
        #pragma unroll
        for (int mi = 0; mi < MT_W; ++mi)
            #pragma unroll
            for (int ni = 0; ni < NT_W; ++ni)
                #pragma unroll
                for (int k = 0; k < 4; ++k) acc[mi][ni][k] = 0.0f;

        // prologue: issue chunk 0
        {
            const float* src = wsrc;
            for (int i = tid; i < PIECES; i += NT) {
                int row = i / (OC / 4), col = i % (OC / 4);
                cp_async16(wb_u32[0] + (row * WBS + col * 4) * 4,
                           src + row * OC + col * 4);
            }
            asm volatile("cp.async.commit_group;");
        }

        for (int kc = 0; kc < NKCH; ++kc) {
            if (kc + 1 < NKCH) {      // issue next chunk into other buffer
                const float* src = wsrc + (size_t)(kc + 1) * KCH * OC;
                uint32_t db = wb_u32[(kc + 1) & 1];
                for (int i = tid; i < PIECES; i += NT) {
                    int row = i / (OC / 4), col = i % (OC / 4);
                    cp_async16(db + (row * WBS + col * 4) * 4,
                               src + row * OC + col * 4);
                }
                asm volatile("cp.async.commit_group;");
                asm volatile("cp.async.wait_group 1;");
            } else {
                asm volatile("cp.async.wait_group 0;");
            }
            __syncthreads();                   // chunk kc visible to all

            const float* wb = s_wb[kc & 1];
            #pragma unroll
            for (int s = 0; s < KCH / 8; ++s) {    // 8 s-steps
                uint32_t a[MT_W][4];
                const float* sa = s_in + (kc * (KCH / 4) + s * 2) * CH;
                #pragma unroll
                for (int mi = 0; mi < MT_W; ++mi) {
                    a[mi][0] = __float_as_uint(sa[roff[mi][0]]);
                    a[mi][1] = __float_as_uint(sa[roff[mi][1]]);
                    a[mi][2] = __float_as_uint(sa[roff[mi][0] + CH]);
                    a[mi][3] = __float_as_uint(sa[roff[mi][1] + CH]);
                }
                const float* sb = wb + s * 8 * WBS + bboff;
                #pragma unroll
                for (int ni = 0; ni < NT_W; ++ni) {
                    int n0 = (ng * NT_W + ni) * 8;
                    uint32_t bb0 = __float_as_uint(sb[n0]);
                    uint32_t bb1 = __float_as_uint(sb[n0 + 4 * WBS]);
                    #pragma unroll
                    for (int mi = 0; mi < MT_W; ++mi)
                        mma_tf32(acc[mi][ni], a[mi], bb0, bb1);
                }
            }
            __syncthreads();                   // buffer kc free for reuse
        }

        // epilogue: bias + relu, NCHW scatter
        #pragma unroll
        for (int mi = 0; mi < MT_W; ++mi) {
            int m0 = (mg + mi * MGROUPS) * 16;
            int bl = m0 / Q;
            int q0 = m0 % Q;
            #pragma unroll
            for (int ni = 0; ni < NT_W; ++ni) {
                int oc = (ng * NT_W + ni) * 8 + 2 * kq;
                float bv0 = bias[oc], bv1 = bias[oc + 1];
                #pragma unroll
                for (int h = 0; h < 2; ++h) {
                    int q = q0 + ln4 + h * 8;
                    int jy = q / JW, jx = q % JW;
                    int oy = 2 * jy + py, ox = 2 * jx + px;
                    size_t o = (((size_t)(b0 + bl) * OC + oc) * OH + oy) * OW + ox;
                    float v0 = fmaxf(acc[mi][ni][2 * h + 0] + bv0, 0.0f);
                    float v1 = fmaxf(acc[mi][ni][2 * h + 1] + bv1, 0.0f);
                    out[o] = v0;
                    out[o + (size_t)OH * OW] = v1;
                }
            }
        }
    }
}

// ---------------- ConvTranspose2d direct fp32 (conv3 only) -----------------
template <int IC, int OC, int IH, int IW, int OHT, int OCT, int TOC, int Q,
          int ICC, bool RELU, int NT>
__global__ __launch_bounds__(NT) void convt_kernel(
    const float* __restrict__ in, const float* __restrict__ W,
    const float* __restrict__ bias, float* __restrict__ out) {
    constexpr int OH = 2 * IH, OW = 2 * IW;
    constexpr int NQY = OHT / 2, NQX = OW / 2, XG = NQX / Q;
    constexpr int SROWS = NQY + 2, SCOLS = IW + 2;
    constexpr int IN_ELE = IC * SROWS * SCOLS;
    constexpr int WSTR = 17;

    extern __shared__ float smem[];
    float* s_in = smem;
    float* s_w = smem + IN_ELE;

    const int b = blockIdx.x;
    const int jy0 = blockIdx.y * NQY;
    const int oc0 = blockIdx.z * OCT;

    const int tid = threadIdx.x;
    const int sp = tid % (NQY * XG);
    const int ocg = tid / (NQY * XG);
    const int qxg = sp % XG;
    const int qy = sp / XG;
    const int qx0 = qxg * Q;

    const float* inb = in + (size_t)b * IC * IH * IW;
    for (int idx = tid; idx < IN_ELE; idx += NT) {
        int ic = idx / (SROWS * SCOLS);
        int r = idx % (SROWS * SCOLS);
        int ry = r / SCOLS, cx = r % SCOLS;
        int iy = jy0 - 1 + ry, ix = cx - 1;
        float v = 0.0f;
        if (iy >= 0 && iy < IH && ix >= 0 && ix < IW)
            v = inb[(ic * IH + iy) * IW + ix];
        s_in[idx] = v;
    }

    float acc[TOC][Q][4];
    #pragma unroll
    for (int t = 0; t < TOC; ++t)
        #pragma unroll
        for (int q = 0; q < Q; ++q)
            #pragma unroll
            for (int k = 0; k < 4; ++k) acc[t][q][k] = 0.0f;

    for (int ic0 = 0; ic0 < IC; ic0 += ICC) {
        __syncthreads();
        for (int idx = tid; idx < ICC * OCT * 16; idx += NT) {
            int k = idx & 15;
            int ol = (idx >> 4) % OCT;
            int icl = idx / (16 * OCT);
            s_w[(icl * OCT + ol) * WSTR + k] =
                W[((size_t)(ic0 + icl) * OC + oc0 + ol) * 16 + k];
        }
        __syncthreads();

        for (int icl = 0; icl < ICC; ++icl) {
            const float* si =
                s_in + (ic0 + icl) * (SROWS * SCOLS) + qy * SCOLS + qx0;
            float iv[3][Q + 2];
            #pragma unroll
            for (int r = 0; r < 3; ++r)
                #pragma unroll
                for (int c = 0; c < Q + 2; ++c) iv[r][c] = si[r * SCOLS + c];

            #pragma unroll
            for (int t = 0; t < TOC; ++t) {
                const float* wp = s_w + (icl * OCT + ocg * TOC + t) * WSTR;
                float w[16];
                #pragma unroll
                for (int k = 0; k < 16; ++k) w[k] = wp[k];
                #pragma unroll
                for (int q = 0; q < Q; ++q) {
                    float* a = acc[t][q];
                    a[0] += iv[0][q] * w[15];     a[0] += iv[0][q + 1] * w[13];
                    a[0] += iv[1][q] * w[7];      a[0] += iv[1][q + 1] * w[5];
                    a[1] += iv[0][q + 1] * w[14]; a[1] += iv[0][q + 2] * w[12];
                    a[1] += iv[1][q + 1] * w[6];  a[1] += iv[1][q + 2] * w[4];
                    a[2] += iv[1][q] * w[11];     a[2] += iv[1][q + 1] * w[9];
                    a[2] += iv[2][q] * w[3];      a[2] += iv[2][q + 1] * w[1];
                    a[3] += iv[1][q + 1] * w[10]; a[3] += iv[1][q + 2] * w[8];
                    a[3] += iv[2][q + 1] * w[2];  a[3] += iv[2][q + 2] * w[0];
                }
            }
        }
    }

    float* outb = out + (size_t)b * OC * OH * OW;
    #pragma unroll
    for (int t = 0; t < TOC; ++t) {
        int oc = oc0 + ocg * TOC + t;
        float bv = bias[oc];
        #pragma unroll
        for (int q = 0; q < Q; ++q) {
            int ox = 2 * (qx0 + q);
            #pragma unroll
            for (int py = 0; py < 2; ++py) {
                int oy = 2 * (jy0 + qy) + py;
                float v0 = acc[t][q][py * 2 + 0] + bv;
                float v1 = acc[t][q][py * 2 + 1] + bv;
                if (RELU) { v0 = fmaxf(v0, 0.0f); v1 = fmaxf(v1, 0.0f); }
                *reinterpret_cast<float2*>(outb + ((size_t)oc * OH + oy) * OW + ox) =
                    make_float2(v0, v1);
            }
        }
    }
}

// ---------------------------------------------------------------------------
extern "C" void kernel_launch(void* const* d_in, const int* in_sizes, int n_in,
                              void* d_out, int out_size) {
    (void)in_sizes; (void)n_in; (void)out_size;
    const float* x  = (const float*)d_in[0];
    const float* gw = (const float*)d_in[1];
    const float* gb = (const float*)d_in[2];
    const float* z  = (const float*)d_in[3];
    const float* w1 = (const float*)d_in[4];
    const float* b1 = (const float*)d_in[5];
    const float* w2 = (const float*)d_in[6];
    const float* b2 = (const float*)d_in[7];
    const float* w3 = (const float*)d_in[8];
    const float* b3 = (const float*)d_in[9];
    float* out = (float*)d_out;

    float *px0, *pa1, *pa2, *pw1t, *pw2t;
    cudaGetSymbolAddress((void**)&px0, g_x0);
    cudaGetSymbolAddress((void**)&pa1, g_a1);
    cudaGetSymbolAddress((void**)&pa2, g_a2);
    cudaGetSymbolAddress((void**)&pw1t, g_w1t);
    cudaGetSymbolAddress((void**)&pw2t, g_w2t);

    // conv1: JH=8, NB=2, OC=128, 16 warps, MGROUPS=4, NGROUPS=4, MT=2, NT=4
    constexpr int S1 = (2 * 128 * 100 + 2 * 64 * 136) * 4;  // 172,032
    // conv2: JH=16, NB=1, OC=64, 16 warps, MGROUPS=8, NGROUPS=2, MT=2, NT=4
    constexpr int S2 = (1 * 128 * 324 + 2 * 64 * 72) * 4;   // 202,752
    // conv3 (fp32 direct): OHT=32, Q=4
    constexpr int S3 = (64 * 18 * 34 + 64 * 3 * 17) * 4;    // 169,728

    auto k1 = convt_mma_kernel<8, 8, 128, 128, 2, 4, 4, 2, 4, 16, 136>;
    auto k2 = convt_mma_kernel<16, 16, 128, 64, 1, 8, 2, 2, 4, 16, 72>;
    auto k3 = convt_kernel<64, 3, 32, 32, 32, 3, 3, 4, 64, false, 128>;

    cudaFuncSetAttribute(k1, cudaFuncAttributeMaxDynamicSharedMemorySize, S1);
    cudaFuncSetAttribute(k2, cudaFuncAttributeMaxDynamicSharedMemorySize, S2);
    cudaFuncSetAttribute(k3, cudaFuncAttributeMaxDynamicSharedMemorySize, S3);

    wprep_kernel<128, 128><<<(4 * 512 * 128 + 255) / 256, 256>>>(w1, pw1t);
    wprep_kernel<128, 64><<<(4 * 512 * 64 + 255) / 256, 256>>>(w2, pw2t);
    lp_kernel<<<B_, 32>>>(x, gw, gb);
    mix_kernel<<<dim3(8192 / 256, B_ / 32), 256>>>(z);

    k1<<<dim3(B_ / 2), 512, S1>>>(px0, pw1t, b1, pa1);
    k2<<<dim3(B_ / 1), 512, S2>>>(pa1, pw2t, b2, pa2);
    k3<<<dim3(B_, 2, 1), 128, S3>>>(pa2, w3, b3, out);
}

// round 6
// speedup vs baseline: 3.1394x; 1.4361x over previous
#include <cuda_runtime.h>
#include <cuda_fp16.h>
#include <cstdint>

// ---------------------------------------------------------------------------
// MixtureDecoder: soft-tree gating -> leaf mixture -> 3x ConvTranspose2d(4,2,1)
// All three convs: implicit-GEMM fp16 mma.sync m16n8k16 (fp32 accum),
// resident fp16 input in smem, pre-packed half2 weights via cp.async.
// ---------------------------------------------------------------------------

#define B_ 512

__device__ float  g_lp[B_ * 32];                    // leaf probs
__device__ __half g_x0[(size_t)B_ * 128 * 8 * 8];   // mixture out (conv1 in)
__device__ __half g_a1[(size_t)B_ * 128 * 16 * 16]; // conv1 out (relu)
__device__ __half g_a2[(size_t)B_ * 64 * 32 * 32];  // conv2 out (relu)
__device__ uint32_t g_w1t[4 * 256 * 128];           // conv1 W [p][k/2][oc] h2
__device__ uint32_t g_w2t[4 * 256 * 64];            // conv2 W
__device__ uint32_t g_w3t[4 * 128 * 8];             // conv3 W (oc padded to 8)

// ---------------- gating + tree leaf probabilities -------------------------
__global__ void lp_kernel(const float* __restrict__ x,
                          const float* __restrict__ gw,
                          const float* __restrict__ gb) {
    int b = blockIdx.x;
    int lane = threadIdx.x;               // 32 threads
    __shared__ float g_sh[31];

    if (lane < 31) {
        float p = gb[lane];
        const float* xb = x + b * 128;
        #pragma unroll 8
        for (int i = 0; i < 128; ++i)
            p += xb[i] * gw[i * 31 + lane];
        g_sh[lane] = 1.0f / (1.0f + expf(-p));
    }
    __syncwarp();

    float lp = 1.0f;
    int prefix = 0;
    #pragma unroll
    for (int d = 1; d <= 5; ++d) {
        float gate = g_sh[(1 << (d - 1)) - 1 + prefix];
        int bit = (lane >> (5 - d)) & 1;
        lp *= bit ? (1.0f - gate) : gate;
        prefix = (prefix << 1) | bit;
    }
    g_lp[b * 32 + lane] = lp;
}

// ---------------- mixture: x0[b,f] = sum_l lp[b,l] * z[f,l] (fp16 out) -----
__global__ __launch_bounds__(256) void mix_kernel(const float* __restrict__ z) {
    int f = blockIdx.x * 256 + threadIdx.x;
    int b0 = blockIdx.y * 32;
    __shared__ float s_lp[32][32];
    for (int i = threadIdx.x; i < 1024; i += 256)
        s_lp[i >> 5][i & 31] = g_lp[b0 * 32 + i];
    __syncthreads();

    float zr[32];
    #pragma unroll
    for (int l4 = 0; l4 < 8; ++l4) {
        float4 v = *reinterpret_cast<const float4*>(z + (size_t)f * 32 + l4 * 4);
        zr[l4 * 4 + 0] = v.x; zr[l4 * 4 + 1] = v.y;
        zr[l4 * 4 + 2] = v.z; zr[l4 * 4 + 3] = v.w;
    }
    #pragma unroll 4
    for (int bi = 0; bi < 32; ++bi) {
        float acc = 0.0f;
        #pragma unroll
        for (int l = 0; l < 32; ++l) acc += zr[l] * s_lp[bi][l];
        g_x0[(size_t)(b0 + bi) * 8192 + f] = __float2half(acc);
    }
}

// ---------------- helpers ---------------------------------------------------
__device__ __forceinline__ void mma_f16(float* c, const uint32_t* a,
                                        uint32_t b0v, uint32_t b1v) {
    asm volatile(
        "mma.sync.aligned.m16n8k16.row.col.f32.f16.f16.f32 "
        "{%0,%1,%2,%3}, {%4,%5,%6,%7}, {%8,%9}, {%0,%1,%2,%3};\n"
        : "+f"(c[0]), "+f"(c[1]), "+f"(c[2]), "+f"(c[3])
        : "r"(a[0]), "r"(a[1]), "r"(a[2]), "r"(a[3]), "r"(b0v), "r"(b1v));
}

__device__ __forceinline__ void cp_async16(uint32_t dst, const void* src) {
    asm volatile("cp.async.cg.shared.global [%0], [%1], 16;"
                 :: "r"(dst), "l"(src));
}

__device__ __forceinline__ uint32_t pk2(const __half* p) {
    uint32_t lo = *reinterpret_cast<const unsigned short*>(p);
    uint32_t hi = *reinterpret_cast<const unsigned short*>(p + 1);
    return lo | (hi << 16);
}

__device__ __forceinline__ void stv(__half* p, float v) { *p = __float2half(v); }
__device__ __forceinline__ void stv(float* p, float v) { *p = v; }

// ---------------- weight pre-pack: W[ic][ocv][4][4] -> [p][k/2][ocp] half2 --
// k = ic*4 + tap, tap=(ddy*2+ddx); ky = 3-py-2*ddy, kx = 3-px-2*ddx.
template <int IC, int OCP, int OCV>
__global__ __launch_bounds__(256) void wprep_kernel(const float* __restrict__ W,
                                                    uint32_t* __restrict__ Wt) {
    constexpr int K2 = 2 * IC;                // K/2
    int idx = blockIdx.x * 256 + threadIdx.x;
    if (idx >= 4 * K2 * OCP) return;
    int n = idx % OCP;
    int pr = (idx / OCP) % K2;
    int p = idx / (OCP * K2);
    int py = p >> 1, px = p & 1;
    __half h[2];
    #pragma unroll
    for (int j = 0; j < 2; ++j) {
        int k = 2 * pr + j;
        int ic = k >> 2;
        int ddy = (k >> 1) & 1, ddx = k & 1;
        int ky = 3 - py - 2 * ddy, kx = 3 - px - 2 * ddx;
        float v = (n < OCV) ? W[((size_t)ic * OCV + n) * 16 + ky * 4 + kx] : 0.0f;
        h[j] = __float2half(v);
    }
    Wt[idx] = (uint32_t)*reinterpret_cast<unsigned short*>(&h[0])
            | ((uint32_t)*reinterpret_cast<unsigned short*>(&h[1]) << 16);
}

// ---------------- ConvT(4,2,1) implicit GEMM, fp16 m16n8k16 ----------------
// Per parity (py,px): out quad (jy,jx) = GEMM row; k = ic*4 + tap.
// Thread (lane) q=lane&3: dy=q&1, ic offsets {q>>1, q>>1+2} in each 4-ic
// group; k-pair = dx in {0,1} = two x-adjacent input halfs.
// s_in: [NB][IC][JH+2][JW+2] fp16, zero halo, staged ONCE.
// s_wb: double-buffered [KCH/2 pair-rows][WBS2 u32] half2 weight chunks.
template <int JH, int JW, int IC, int OC, int OCV, int NB,
          int MGROUPS, int NGROUPS, int MT_W, int NT_W, int NWARPS,
          int WBS2, bool RELU, typename TO, int MINB>
__global__ __launch_bounds__(NWARPS * 32, MINB) void convt_mma_kernel(
    const __half* __restrict__ in, const uint32_t* __restrict__ Wt,
    const float* __restrict__ bias, TO* __restrict__ out) {
    constexpr int SR = JW + 2;
    constexpr int CH = (JH + 2) * SR;
    constexpr int KCH = 64;                  // k rows per chunk (16 ics)
    constexpr int KTOT = 4 * IC;
    constexpr int NKCH = KTOT / KCH;
    constexpr int Q = JH * JW;
    constexpr int IN_ELE = NB * IC * CH;     // halfs
    constexpr int NT = NWARPS * 32;
    constexpr int OH = 2 * JH, OW = 2 * JW;
    constexpr int PIECES = (KCH / 2) * (OC / 4);   // 16B pieces per chunk
    constexpr int CHUNK_U32 = (KCH / 2) * WBS2;

    extern __shared__ char smem_raw[];
    __half* s_in = reinterpret_cast<__half*>(smem_raw);
    uint32_t* s_wb[2] = {
        reinterpret_cast<uint32_t*>(smem_raw + IN_ELE * 2),
        reinterpret_cast<uint32_t*>(smem_raw + IN_ELE * 2) + CHUNK_U32};
    uint32_t wb_u32[2] = {(uint32_t)__cvta_generic_to_shared(s_wb[0]),
                          (uint32_t)__cvta_generic_to_shared(s_wb[1])};

    const int tid = threadIdx.x;
    const int lane = tid & 31;
    const int w = tid >> 5;
    const int mg = w % MGROUPS;
    const int ng = w / MGROUPS;
    const int q = lane & 3;                  // k-quad
    const int dy = q & 1;
    const int icq = q >> 1;
    const int ln4 = lane >> 2;

    const int b0 = blockIdx.x * NB;

    // ---- stage full fp16 input, zero halo — ONCE ----
    for (int idx = tid; idx < IN_ELE; idx += NT) {
        int bl = idx / (IC * CH);
        int rem = idx % (IC * CH);
        int ic = rem / CH;
        int rr = rem % CH;
        int ry = rr / SR, cx = rr % SR;
        int iy = ry - 1, ix = cx - 1;
        __half v = __float2half(0.0f);
        if (iy >= 0 && iy < JH && ix >= 0 && ix < JW)
            v = in[(((size_t)(b0 + bl) * IC + ic) * JH + iy) * JW + ix];
        s_in[idx] = v;
    }

    for (int p = 0; p < 4; ++p) {
        const int py = p >> 1, px = p & 1;
        const uint32_t* wsrc = Wt + (size_t)p * (KTOT / 2) * OC;

        // per-thread A base offsets (rows ln4, ln4+8 of each m-tile)
        int roff[MT_W][2];
        #pragma unroll
        for (int mi = 0; mi < MT_W; ++mi) {
            int m0 = (mg + mi * MGROUPS) * 16;
            int bl = m0 / Q;
            int q0 = m0 % Q;
            #pragma unroll
            for (int h = 0; h < 2; ++h) {
                int qq = q0 + ln4 + h * 8;
                int jy = qq / JW, jx = qq % JW;
                roff[mi][h] = bl * (IC * CH) + (jy + dy + py) * SR + (jx + px);
            }
        }

        float acc[MT_W][NT_W][4];
        #pragma unroll
        for (int mi = 0; mi < MT_W; ++mi)
            #pragma unroll
            for (int ni = 0; ni < NT_W; ++ni)
                #pragma unroll
                for (int k = 0; k < 4; ++k) acc[mi][ni][k] = 0.0f;

        // prologue: issue chunk 0
        for (int i = tid; i < PIECES; i += NT) {
            int row = i / (OC / 4), col = i % (OC / 4);
            cp_async16(wb_u32[0] + (row * WBS2 + col * 4) * 4,
                       wsrc + row * OC + col * 4);
        }
        asm volatile("cp.async.commit_group;");

        for (int kc = 0; kc < NKCH; ++kc) {
            if (kc + 1 < NKCH) {
                const uint32_t* src = wsrc + (size_t)(kc + 1) * (KCH / 2) * OC;
                uint32_t db = wb_u32[(kc + 1) & 1];
                for (int i = tid; i < PIECES; i += NT) {
                    int row = i / (OC / 4), col = i % (OC / 4);
                    cp_async16(db + (row * WBS2 + col * 4) * 4,
                               src + row * OC + col * 4);
                }
                asm volatile("cp.async.commit_group;");
                asm volatile("cp.async.wait_group 1;");
            } else {
                asm volatile("cp.async.wait_group 0;");
            }
            __syncthreads();

            const uint32_t* wb = s_wb[kc & 1];
            #pragma unroll
            for (int s = 0; s < KCH / 16; ++s) {   // 4 s-steps (K=16 each)
                const int icb = kc * (KCH / 4) + s * 4 + icq;
                const __half* c0p = s_in + icb * CH;
                const __half* c1p = c0p + 2 * CH;
                uint32_t a[MT_W][4];
                #pragma unroll
                for (int mi = 0; mi < MT_W; ++mi) {
                    a[mi][0] = pk2(c0p + roff[mi][0]);
                    a[mi][1] = pk2(c0p + roff[mi][1]);
                    a[mi][2] = pk2(c1p + roff[mi][0]);
                    a[mi][3] = pk2(c1p + roff[mi][1]);
                }
                const uint32_t* sb = wb + (s * 8 + q) * WBS2 + ln4;
                #pragma unroll
                for (int ni = 0; ni < NT_W; ++ni) {
                    int n0 = (ng * NT_W + ni) * 8;
                    uint32_t bb0 = sb[n0];
                    uint32_t bb1 = sb[n0 + 4 * WBS2];
                    #pragma unroll
                    for (int mi = 0; mi < MT_W; ++mi)
                        mma_f16(acc[mi][ni], a[mi], bb0, bb1);
                }
            }
            __syncthreads();
        }

        // epilogue: bias (+relu), NCHW scatter
        #pragma unroll
        for (int mi = 0; mi < MT_W; ++mi) {
            int m0 = (mg + mi * MGROUPS) * 16;
            int bl = m0 / Q;
            int q0 = m0 % Q;
            #pragma unroll
            for (int ni = 0; ni < NT_W; ++ni) {
                int oc = (ng * NT_W + ni) * 8 + 2 * q;
                bool v0ok = (OCV == OC) || (oc < OCV);
                bool v1ok = (OCV == OC) || (oc + 1 < OCV);
                float bv0 = v0ok ? bias[oc] : 0.0f;
                float bv1 = v1ok ? bias[oc + 1] : 0.0f;
                #pragma unroll
                for (int h = 0; h < 2; ++h) {
                    int qq = q0 + ln4 + h * 8;
                    int jy = qq / JW, jx = qq % JW;
                    int oy = 2 * jy + py, ox = 2 * jx + px;
                    size_t o = (((size_t)(b0 + bl) * OCV + oc) * OH + oy) * OW + ox;
                    float v0 = acc[mi][ni][2 * h + 0] + bv0;
                    float v1 = acc[mi][ni][2 * h + 1] + bv1;
                    if (RELU) { v0 = fmaxf(v0, 0.0f); v1 = fmaxf(v1, 0.0f); }
                    if (v0ok) stv(out + o, v0);
                    if (v1ok) stv(out + o + (size_t)OH * OW, v1);
                }
            }
        }
    }
}

// ---------------------------------------------------------------------------
extern "C" void kernel_launch(void* const* d_in, const int* in_sizes, int n_in,
                              void* d_out, int out_size) {
    (void)in_sizes; (void)n_in; (void)out_size;
    const float* x  = (const float*)d_in[0];
    const float* gw = (const float*)d_in[1];
    const float* gb = (const float*)d_in[2];
    const float* z  = (const float*)d_in[3];
    const float* w1 = (const float*)d_in[4];
    const float* b1 = (const float*)d_in[5];
    const float* w2 = (const float*)d_in[6];
    const float* b2 = (const float*)d_in[7];
    const float* w3 = (const float*)d_in[8];
    const float* b3 = (const float*)d_in[9];
    float* out = (float*)d_out;

    __half *px0, *pa1, *pa2;
    uint32_t *pw1t, *pw2t, *pw3t;
    cudaGetSymbolAddress((void**)&px0, g_x0);
    cudaGetSymbolAddress((void**)&pa1, g_a1);
    cudaGetSymbolAddress((void**)&pa2, g_a2);
    cudaGetSymbolAddress((void**)&pw1t, g_w1t);
    cudaGetSymbolAddress((void**)&pw2t, g_w2t);
    cudaGetSymbolAddress((void**)&pw3t, g_w3t);

    // conv1: JH=8, NB=2, OC=128; MG=4,NG=4,MT=2,NT=4; WBS2=136
    constexpr int S1 = 2 * 128 * 100 * 2 + 2 * 32 * 136 * 4;  // 86,016
    // conv2: JH=16, NB=1, OC=64; MG=8,NG=2,MT=2,NT=4; WBS2=72
    constexpr int S2 = 128 * 324 * 2 + 2 * 32 * 72 * 4;       // 101,376
    // conv3: JH=32, NB=1, OC=8(pad,3 valid); MG=16,NG=1,MT=4,NT=1; WBS2=8
    constexpr int S3 = 64 * 1156 * 2 + 2 * 32 * 8 * 4;        // 150,016

    auto k1 = convt_mma_kernel<8, 8, 128, 128, 128, 2, 4, 4, 2, 4, 16, 136,
                               true, __half, 2>;
    auto k2 = convt_mma_kernel<16, 16, 128, 64, 64, 1, 8, 2, 2, 4, 16, 72,
                               true, __half, 2>;
    auto k3 = convt_mma_kernel<32, 32, 64, 8, 3, 1, 16, 1, 4, 1, 16, 8,
                               false, float, 1>;

    cudaFuncSetAttribute(k1, cudaFuncAttributeMaxDynamicSharedMemorySize, S1);
    cudaFuncSetAttribute(k2, cudaFuncAttributeMaxDynamicSharedMemorySize, S2);
    cudaFuncSetAttribute(k3, cudaFuncAttributeMaxDynamicSharedMemorySize, S3);

    wprep_kernel<128, 128, 128><<<(4 * 256 * 128 + 255) / 256, 256>>>(w1, pw1t);
    wprep_kernel<128, 64, 64><<<(4 * 256 * 64 + 255) / 256, 256>>>(w2, pw2t);
    wprep_kernel<64, 8, 3><<<(4 * 128 * 8 + 255) / 256, 256>>>(w3, pw3t);
    lp_kernel<<<B_, 32>>>(x, gw, gb);
    mix_kernel<<<dim3(8192 / 256, B_ / 32), 256>>>(z);

    k1<<<dim3(B_ / 2), 512, S1>>>(px0, pw1t, b1, pa1);
    k2<<<dim3(B_), 512, S2>>>(pa1, pw2t, b2, pa2);
    k3<<<dim3(B_), 512, S3>>>(pa2, pw3t, b3, out);
}